// round 15
// baseline (speedup 1.0000x reference)
#include <cuda_runtime.h>
#include <cuda_bf16.h>
#include <math.h>
#include <stdint.h>

// Problem constants
#define NROWS 2048      // B*N
#define DIM   1024      // D
#define MKEYS 32768     // M
#define TK    32        // top-k
#define NH    16        // heads
#define HDIM  64        // head dim

// ================= scratch (device globals) =================
__device__ float g_qfull[NROWS * DIM];
__device__ float g_ctx[NROWS * DIM];
__device__ float g_c[MKEYS];
__device__ int   g_sel[2][TK];
__device__ float g_Kt[2][DIM * TK];      // projected keys, transposed [o][k]
__device__ float g_V[2][TK * DIM];       // projected values [k][o]
__device__ float g_att[NROWS * (NH * TK)];
__device__ unsigned long long g_part[2][16][TK];
__device__ float g_qmp[8 * NROWS];
__device__ float g_pp[2 * 16 * 64 * DIM];   // selproj partials [kv][ds][row64][o]

// ================= PTX helpers =================
__device__ __forceinline__ uint32_t smem_u32(const void* p) {
    uint32_t a;
    asm("{ .reg .u64 t; cvta.to.shared.u64 t, %1; cvt.u32.u64 %0, t; }" : "=r"(a) : "l"(p));
    return a;
}
__device__ __forceinline__ void ldsm4(uint32_t* r, uint32_t addr) {
    asm volatile("ldmatrix.sync.aligned.m8n8.x4.shared.b16 {%0,%1,%2,%3}, [%4];"
        : "=r"(r[0]), "=r"(r[1]), "=r"(r[2]), "=r"(r[3]) : "r"(addr));
}
__device__ __forceinline__ void mma16816(float* c, const uint32_t* a, const uint32_t* b) {
    asm volatile("mma.sync.aligned.m16n8k16.row.col.f32.bf16.bf16.f32 "
        "{%0,%1,%2,%3}, {%4,%5,%6,%7}, {%8,%9}, {%0,%1,%2,%3};"
        : "+f"(c[0]), "+f"(c[1]), "+f"(c[2]), "+f"(c[3])
        : "r"(a[0]), "r"(a[1]), "r"(a[2]), "r"(a[3]), "r"(b[0]), "r"(b[1]));
}
__device__ __forceinline__ uint32_t cvt_bf2(float lo, float hi) {
    uint32_t r;
    asm("cvt.rn.bf16x2.f32 %0, %1, %2;" : "=r"(r) : "f"(hi), "f"(lo));
    return r;
}

// ================= 1) per-memory-row stats =================
__global__ void stats_kernel(const float* __restrict__ keys) {
    int warp = (blockIdx.x * blockDim.x + threadIdx.x) >> 5;
    int lane = threadIdx.x & 31;
    if (warp >= MKEYS) return;
    const float4* p = (const float4*)(keys + (size_t)warp * DIM);
    float s = 0.f, sq = 0.f;
#pragma unroll
    for (int i = 0; i < 8; i++) {
        float4 v = p[lane + i * 32];
        s  += v.x + v.y + v.z + v.w;
        sq += v.x * v.x + v.y * v.y + v.z * v.z + v.w * v.w;
    }
#pragma unroll
    for (int o = 16; o; o >>= 1) {
        s  += __shfl_xor_sync(0xffffffffu, s, o);
        sq += __shfl_xor_sync(0xffffffffu, sq, o);
    }
    if (lane == 0) g_c[warp] = s / (32.0f * sqrtf(sq));
}

// ================= 2) top-32 =================
__device__ __forceinline__ unsigned long long tk_make_key(float f, int m) {
    unsigned b = __float_as_uint(f);
    unsigned k = (b & 0x80000000u) ? ~b : (b | 0x80000000u);
    return ((unsigned long long)k << 32) | (unsigned long long)(0xFFFFFFFFu - (unsigned)m);
}
__device__ __forceinline__ unsigned long long tk_sort_asc(unsigned long long v) {
    unsigned lane = threadIdx.x & 31;
#pragma unroll
    for (int k = 2; k <= 32; k <<= 1) {
#pragma unroll
        for (int j = k >> 1; j > 0; j >>= 1) {
            unsigned long long o = __shfl_xor_sync(0xffffffffu, v, j);
            bool up = ((lane & k) == 0), lower = ((lane & j) == 0);
            unsigned long long mn = v < o ? v : o, mx = v < o ? o : v;
            v = (up == lower) ? mn : mx;
        }
    }
    return v;
}
__device__ __forceinline__ unsigned long long tk_bmerge_asc(unsigned long long v) {
    unsigned lane = threadIdx.x & 31;
#pragma unroll
    for (int j = 16; j > 0; j >>= 1) {
        unsigned long long o = __shfl_xor_sync(0xffffffffu, v, j);
        unsigned long long mn = v < o ? v : o, mx = v < o ? o : v;
        v = ((lane & j) == 0) ? mn : mx;
    }
    return v;
}
__global__ void __launch_bounds__(1024) topk_part() {
    int set = blockIdx.y, p = blockIdx.x;
    int lane = threadIdx.x & 31, w = threadIdx.x >> 5;
    __shared__ unsigned long long sh[32][33];
    float sgn = set ? -1.f : 1.f;
    int base = p * 2048 + w * 64;
    int i0 = base + lane, i1 = base + 32 + lane;
    float f0 = sgn * g_c[i0], f1 = sgn * g_c[i1];
    unsigned long long a = tk_sort_asc(tk_make_key(f0, i0));
    unsigned long long b = tk_sort_asc(tk_make_key(f1, i1));
    unsigned long long o = __shfl_sync(0xffffffffu, b, 31 - lane);
    unsigned long long v = a > o ? a : o;
    a = tk_bmerge_asc(v);
    sh[w][lane] = a;
    __syncthreads();
#pragma unroll
    for (int st = 1; st < 32; st <<= 1) {
        if (w < 16 / st) {
            unsigned long long A = sh[2 * w * st][lane];
            unsigned long long B = sh[(2 * w + 1) * st][31 - lane];
            unsigned long long m = A > B ? A : B;
            m = tk_bmerge_asc(m);
            sh[2 * w * st][lane] = m;
        }
        __syncthreads();
    }
    if (w == 0) g_part[set][p][lane] = sh[0][lane];
}
__global__ void __launch_bounds__(512) topk_merge() {
    int set = blockIdx.x;
    int lane = threadIdx.x & 31, w = threadIdx.x >> 5;
    __shared__ unsigned long long sh[16][33];
    sh[w][lane] = g_part[set][w][lane];
    __syncthreads();
#pragma unroll
    for (int st = 1; st < 16; st <<= 1) {
        if (w < 8 / st) {
            unsigned long long A = sh[2 * w * st][lane];
            unsigned long long B = sh[(2 * w + 1) * st][31 - lane];
            unsigned long long m = A > B ? A : B;
            m = tk_bmerge_asc(m);
            sh[2 * w * st][lane] = m;
        }
        __syncthreads();
    }
    if (w == 0) {
        unsigned long long v = sh[0][lane];
        int m = (int)(0xFFFFFFFFu - (unsigned)(v & 0xFFFFFFFFull));
        g_sel[set][31 - lane] = m;
    }
}

// ================= 3) HMMA bf16x3 GEMM with fused fp32->hi/lo split =================
// round-13 proven structure: single buffer, static smem, 2 syncs/iter
#define BK 32
#define NK (DIM / BK)
#define SSTRIDE 40

__global__ void __launch_bounds__(256) mma_gemm(
    const float* __restrict__ A, const float* __restrict__ B,
    float* __restrict__ C, const float* __restrict__ bias,
    float* __restrict__ qmp, int m_off) {
    __shared__ __align__(16) __nv_bfloat16 sm[4][128 * SSTRIDE];
    __shared__ float sq[4][128];
    int tid = threadIdx.x, lane = tid & 31, wid = tid >> 5;
    int bm = m_off + blockIdx.y * 128, bn = blockIdx.x * 128;
    int wm = wid >> 2, wn = wid & 3;
    int m0 = wm * 64, n0 = wn * 32;

    const float* srcs[2] = { A + (size_t)bm * DIM, B + (size_t)bn * DIM };

    uint32_t sbase[4];
#pragma unroll
    for (int t = 0; t < 4; t++) sbase[t] = smem_u32(sm[t]);

    int a_ro = (m0 + (lane & 15)) * SSTRIDE + ((lane & 16) ? 8 : 0);
    int b_ro = (n0 + (lane & 7) + ((lane & 16) ? 8 : 0)) * SSTRIDE + ((lane & 8) ? 8 : 0);

    float acc[4][4][4];
#pragma unroll
    for (int i = 0; i < 4; i++)
#pragma unroll
        for (int j = 0; j < 4; j++)
#pragma unroll
            for (int r = 0; r < 4; r++) acc[i][j][r] = 0.f;

    float4 pf[8];
#pragma unroll
    for (int t = 0; t < 2; t++)
#pragma unroll
        for (int u = 0; u < 4; u++) {
            int c = tid + u * 256, row = c >> 3, fc = c & 7;
            pf[t * 4 + u] = *(const float4*)(srcs[t] + (size_t)row * DIM + fc * 4);
        }

#pragma unroll 1
    for (int kt = 0; kt < NK; kt++) {
#pragma unroll
        for (int t = 0; t < 2; t++)
#pragma unroll
            for (int u = 0; u < 4; u++) {
                int c = tid + u * 256, row = c >> 3, fc = c & 7;
                float4 v = pf[t * 4 + u];
                uint32_t h01 = cvt_bf2(v.x, v.y), h23 = cvt_bf2(v.z, v.w);
                float l0 = v.x - __uint_as_float(h01 << 16);
                float l1 = v.y - __uint_as_float(h01 & 0xFFFF0000u);
                float l2 = v.z - __uint_as_float(h23 << 16);
                float l3 = v.w - __uint_as_float(h23 & 0xFFFF0000u);
                uint32_t l01 = cvt_bf2(l0, l1), l23 = cvt_bf2(l2, l3);
                *(uint2*)(&sm[t * 2][row * SSTRIDE + fc * 4]) = make_uint2(h01, h23);
                *(uint2*)(&sm[t * 2 + 1][row * SSTRIDE + fc * 4]) = make_uint2(l01, l23);
            }
        __syncthreads();
        if (kt + 1 < NK) {
#pragma unroll
            for (int t = 0; t < 2; t++)
#pragma unroll
                for (int u = 0; u < 4; u++) {
                    int c = tid + u * 256, row = c >> 3, fc = c & 7;
                    pf[t * 4 + u] = *(const float4*)(srcs[t] + (size_t)row * DIM + (kt + 1) * BK + fc * 4);
                }
        }
#pragma unroll
        for (int ks = 0; ks < 2; ks++) {
            uint32_t ah[4][4], al[4][4];
#pragma unroll
            for (int mt = 0; mt < 4; mt++) {
                uint32_t off = 2u * (uint32_t)(a_ro + mt * 16 * SSTRIDE + ks * 16);
                ldsm4(ah[mt], sbase[0] + off);
                ldsm4(al[mt], sbase[1] + off);
            }
            uint32_t bh[4][2], bl[4][2];
#pragma unroll
            for (int pr = 0; pr < 2; pr++) {
                uint32_t off = 2u * (uint32_t)(b_ro + pr * 16 * SSTRIDE + ks * 16);
                uint32_t r[4];
                ldsm4(r, sbase[2] + off);
                bh[pr * 2][0] = r[0]; bh[pr * 2][1] = r[1];
                bh[pr * 2 + 1][0] = r[2]; bh[pr * 2 + 1][1] = r[3];
                ldsm4(r, sbase[3] + off);
                bl[pr * 2][0] = r[0]; bl[pr * 2][1] = r[1];
                bl[pr * 2 + 1][0] = r[2]; bl[pr * 2 + 1][1] = r[3];
            }
#pragma unroll
            for (int mt = 0; mt < 4; mt++)
#pragma unroll
                for (int nt = 0; nt < 4; nt++) {
                    mma16816(acc[mt][nt], ah[mt], bh[nt]);
                    mma16816(acc[mt][nt], ah[mt], bl[nt]);
                    mma16816(acc[mt][nt], al[mt], bh[nt]);
                }
        }
        __syncthreads();
    }

    int gid = lane >> 2, tig = lane & 3;
#pragma unroll
    for (int mt = 0; mt < 4; mt++)
#pragma unroll
        for (int nt = 0; nt < 4; nt++) {
            int row = bm + m0 + mt * 16 + gid;
            int col = bn + n0 + nt * 8 + tig * 2;
            float b0 = 0.f, b1 = 0.f;
            if (bias) { b0 = bias[col]; b1 = bias[col + 1]; }
            float2 v0 = make_float2(acc[mt][nt][0] + b0, acc[mt][nt][1] + b1);
            float2 v1 = make_float2(acc[mt][nt][2] + b0, acc[mt][nt][3] + b1);
            *(float2*)(C + (size_t)row * DIM + col) = v0;
            *(float2*)(C + (size_t)(row + 8) * DIM + col) = v1;
        }

    if (qmp) {
#pragma unroll
        for (int mt = 0; mt < 4; mt++) {
            float p0 = 0.f, p1 = 0.f;
#pragma unroll
            for (int nt = 0; nt < 4; nt++) {
                p0 += acc[mt][nt][0] + acc[mt][nt][1];
                p1 += acc[mt][nt][2] + acc[mt][nt][3];
            }
            p0 += __shfl_xor_sync(0xffffffffu, p0, 1);
            p0 += __shfl_xor_sync(0xffffffffu, p0, 2);
            p1 += __shfl_xor_sync(0xffffffffu, p1, 1);
            p1 += __shfl_xor_sync(0xffffffffu, p1, 2);
            if (tig == 0) {
                sq[wn][m0 + mt * 16 + gid] = p0;
                sq[wn][m0 + mt * 16 + gid + 8] = p1;
            }
        }
        __syncthreads();
        if (tid < 128) {
            float s = sq[0][tid] + sq[1][tid] + sq[2][tid] + sq[3][tid];
            qmp[(size_t)blockIdx.x * NROWS + bm + tid] = s;
        }
    }
}

// ================= 4) selproj split-K + reduce =================
__global__ void __launch_bounds__(256) selproj_part(const float* __restrict__ keys,
                                                    const float* __restrict__ vals,
                                                    const float* __restrict__ Wk,
                                                    const float* __restrict__ Wv) {
    int o0 = blockIdx.x * 64, ds = blockIdx.y, kv = blockIdx.z;
    int d0 = ds * 64;
    const float* S = kv ? vals : keys;
    const float* W = kv ? Wv : Wk;
    __shared__ float Ss[64][68];
    __shared__ float Wt[64][65];
    __shared__ int sel[64];
    int tid = threadIdx.x;
    if (tid < 64) sel[tid] = g_sel[tid >> 5][tid & 31];
    __syncthreads();
#pragma unroll
    for (int u = 0; u < 4; u++) {
        int c = tid + u * 256;
        int r = c >> 4, c4 = c & 15;
        float4 v = *(const float4*)(S + (size_t)sel[r] * DIM + d0 + c4 * 4);
        *(float4*)(&Ss[r][c4 * 4]) = v;
    }
#pragma unroll
    for (int u = 0; u < 4; u++) {
        int c = tid + u * 256;
        int orow = c >> 4, c4 = c & 15;
        float4 v = *(const float4*)(W + (size_t)(o0 + orow) * DIM + d0 + c4 * 4);
        Wt[c4 * 4 + 0][orow] = v.x;
        Wt[c4 * 4 + 1][orow] = v.y;
        Wt[c4 * 4 + 2][orow] = v.z;
        Wt[c4 * 4 + 3][orow] = v.w;
    }
    __syncthreads();

    int ol = tid & 63, rbase = (tid >> 6) * 16;
    float acc[16];
#pragma unroll
    for (int i = 0; i < 16; i++) acc[i] = 0.f;
#pragma unroll 1
    for (int d = 0; d < 64; d += 4) {
        float w0 = Wt[d][ol], w1 = Wt[d + 1][ol], w2 = Wt[d + 2][ol], w3 = Wt[d + 3][ol];
#pragma unroll
        for (int r = 0; r < 16; r++) {
            float4 s = *(const float4*)(&Ss[rbase + r][d]);
            acc[r] += s.x * w0 + s.y * w1 + s.z * w2 + s.w * w3;
        }
    }
    float* dst = g_pp + ((size_t)(kv * 16 + ds) * 64) * DIM;
#pragma unroll
    for (int r = 0; r < 16; r++)
        dst[(size_t)(rbase + r) * DIM + o0 + ol] = acc[r];
}

__global__ void __launch_bounds__(256) selproj_reduce() {
    int idx = blockIdx.x * 256 + threadIdx.x;
    int kv = idx >> 16;
    int rem = idx & 65535;
    int r = rem >> 10, o = rem & 1023;
    const float* src = g_pp + (size_t)(kv * 16) * 64 * DIM + (size_t)r * DIM + o;
    float s = 0.f;
#pragma unroll
    for (int ds = 0; ds < 16; ds++) s += src[(size_t)ds * 64 * DIM];
    int set = r >> 5, k = r & 31;
    if (kv == 0) g_Kt[set][(size_t)o * TK + k] = s;
    else         g_V[set][(size_t)k * DIM + o] = s;
}

// ================= 5a) attention scores + softmax (qm folded) =================
__global__ void __launch_bounds__(256) attn_scores() {
    int h = blockIdx.x;
    int r0 = blockIdx.y * 64;
    __shared__ float qs[64][65];
    __shared__ float Ks[2][64][33];
    __shared__ int sets[64];
    int tid = threadIdx.x;
#pragma unroll
    for (int u = 0; u < 4; u++) {
        int c = tid + u * 256;
        int r = c >> 4, q4 = c & 15;
        float4 v = *(const float4*)(g_qfull + (size_t)(r0 + r) * DIM + h * HDIM + q4 * 4);
        qs[r][q4 * 4 + 0] = v.x; qs[r][q4 * 4 + 1] = v.y; qs[r][q4 * 4 + 2] = v.z; qs[r][q4 * 4 + 3] = v.w;
    }
#pragma unroll
    for (int u = 0; u < 4; u++) {
        int c = tid + u * 256;
        int s = c >> 9, rem = c & 511, j = rem >> 3, k4 = rem & 7;
        float4 v = *(const float4*)(&g_Kt[s][(size_t)(h * HDIM + j) * TK + k4 * 4]);
        Ks[s][j][k4 * 4 + 0] = v.x; Ks[s][j][k4 * 4 + 1] = v.y; Ks[s][j][k4 * 4 + 2] = v.z; Ks[s][j][k4 * 4 + 3] = v.w;
    }
    if (tid < 64) {
        float ss = 0.f;
#pragma unroll
        for (int j = 0; j < 8; j++) ss += g_qmp[(size_t)j * NROWS + r0 + tid];
        sets[tid] = (ss >= 0.f) ? 0 : 1;
    }
    __syncthreads();
    int r = tid >> 2, kg = tid & 3;
    int s = sets[r];
    float sc[8];
#pragma unroll
    for (int kk = 0; kk < 8; kk++) sc[kk] = 0.f;
#pragma unroll
    for (int j = 0; j < 64; j++) {
        float qv = qs[r][j];
#pragma unroll
        for (int kk = 0; kk < 8; kk++) sc[kk] += qv * Ks[s][j][kg * 8 + kk];
    }
    float mx = -INFINITY;
#pragma unroll
    for (int kk = 0; kk < 8; kk++) { sc[kk] *= 0.125f; mx = fmaxf(mx, sc[kk]); }
#pragma unroll
    for (int o = 1; o <= 2; o <<= 1) mx = fmaxf(mx, __shfl_xor_sync(0xffffffffu, mx, o));
    float e[8]; float sum = 0.f;
#pragma unroll
    for (int kk = 0; kk < 8; kk++) { e[kk] = expf(sc[kk] - mx); sum += e[kk]; }
#pragma unroll
    for (int o = 1; o <= 2; o <<= 1) sum += __shfl_xor_sync(0xffffffffu, sum, o);
    float inv = 1.f / sum;
    float* dst = &g_att[(size_t)(r0 + r) * (NH * TK) + h * TK + kg * 8];
    *(float4*)(dst)     = make_float4(e[0] * inv, e[1] * inv, e[2] * inv, e[3] * inv);
    *(float4*)(dst + 4) = make_float4(e[4] * inv, e[5] * inv, e[6] * inv, e[7] * inv);
}

// ================= 5b) context + avg_attn + sel_idx (qm folded) =================
__global__ void __launch_bounds__(256) attn_ctx(float* __restrict__ out_avg,
                                                float* __restrict__ out_sel) {
    int r0 = blockIdx.x * 16;
    __shared__ float att[16][NH * 33];
    __shared__ int sets[16];
    int tid = threadIdx.x;
    if (tid < 16) {
        float ss = 0.f;
#pragma unroll
        for (int j = 0; j < 8; j++) ss += g_qmp[(size_t)j * NROWS + r0 + tid];
        sets[tid] = (ss >= 0.f) ? 0 : 1;
    }
#pragma unroll
    for (int u = 0; u < 8; u++) {
        int c = tid + u * 256;
        int r = c >> 7, rem = c & 127;
        float4 v = *(const float4*)(&g_att[(size_t)(r0 + r) * (NH * TK) + rem * 4]);
        int hh = (rem * 4) >> 5, k = (rem * 4) & 31;
        float* d = &att[r][hh * 33 + k];
        d[0] = v.x; d[1] = v.y; d[2] = v.z; d[3] = v.w;
    }
    __syncthreads();
#pragma unroll
    for (int u = 0; u < 2; u++) {
        int c = tid + u * 256;
        int r = c >> 5, k = c & 31;
        float sm = 0.f;
#pragma unroll
        for (int hh = 0; hh < NH; hh++) sm += att[r][hh * 33 + k];
        out_avg[(size_t)(r0 + r) * TK + k] = sm * (1.f / NH);
        out_sel[(size_t)(r0 + r) * TK + k] = (float)g_sel[sets[r]][k];
    }
#pragma unroll 1
    for (int c = 0; c < 4; c++) {
        int o = c * 256 + tid;
        int h = o >> 6;
        float vv0[32], vv1[32];
#pragma unroll
        for (int k = 0; k < 32; k++) {
            vv0[k] = g_V[0][(size_t)k * DIM + o];
            vv1[k] = g_V[1][(size_t)k * DIM + o];
        }
#pragma unroll 1
        for (int r = 0; r < 16; r++) {
            const float* a = &att[r][h * 33];
            float sum = 0.f;
            if (sets[r]) {
#pragma unroll
                for (int k = 0; k < 32; k++) sum += a[k] * vv1[k];
            } else {
#pragma unroll
                for (int k = 0; k < 32; k++) sum += a[k] * vv0[k];
            }
            g_ctx[(size_t)(r0 + r) * DIM + o] = sum;
        }
    }
}

// ================= 6) LayerNorm (r_base for half-splits) =================
__global__ void __launch_bounds__(256) ln_kernel(int r_base,
                                                 const float* __restrict__ X,
                                                 const float* __restrict__ gamma,
                                                 const float* __restrict__ beta,
                                                 float* __restrict__ out) {
    int row = r_base + blockIdx.x;
    __shared__ float red[256];
    int t = threadIdx.x;
    const float* p = X + (size_t)row * DIM;
    float4 v = ((const float4*)p)[t];
    float s = v.x + v.y + v.z + v.w;
    red[t] = s; __syncthreads();
    for (int off = 128; off; off >>= 1) { if (t < off) red[t] += red[t + off]; __syncthreads(); }
    float mu = red[0] * (1.f / DIM);
    __syncthreads();
    float d0 = v.x - mu, d1 = v.y - mu, d2 = v.z - mu, d3 = v.w - mu;
    red[t] = d0 * d0 + d1 * d1 + d2 * d2 + d3 * d3;
    __syncthreads();
    for (int off = 128; off; off >>= 1) { if (t < off) red[t] += red[t + off]; __syncthreads(); }
    float inv = rsqrtf(red[0] * (1.f / DIM) + 1e-5f);
    float4 g = ((const float4*)gamma)[t];
    float4 b = ((const float4*)beta)[t];
    float4 o;
    o.x = d0 * inv * g.x + b.x;
    o.y = d1 * inv * g.y + b.y;
    o.z = d2 * inv * g.z + b.z;
    o.w = d3 * inv * g.w + b.w;
    ((float4*)(out + (size_t)row * DIM))[t] = o;
}

// ================= launch =================
extern "C" void kernel_launch(void* const* d_in, const int* in_sizes, int n_in,
                              void* d_out, int out_size) {
    const float* q    = (const float*)d_in[0];
    const float* mk   = (const float*)d_in[1];
    const float* mv   = (const float*)d_in[2];
    const float* Wq   = (const float*)d_in[3];
    const float* Wk   = (const float*)d_in[4];
    const float* Wv   = (const float*)d_in[5];
    const float* Wo   = (const float*)d_in[6];
    const float* bo   = (const float*)d_in[7];
    const float* gamma = (const float*)d_in[8];
    const float* beta  = (const float*)d_in[9];
    float* out = (float*)d_out;

    float *p_qfull, *p_ctx, *p_qmp;
    cudaGetSymbolAddress((void**)&p_qfull, g_qfull);
    cudaGetSymbolAddress((void**)&p_ctx, g_ctx);
    cudaGetSymbolAddress((void**)&p_qmp, g_qmp);

    float* out_main = out;
    float* out_avg  = out + (size_t)NROWS * DIM;
    float* out_sel  = out + (size_t)NROWS * DIM + (size_t)NROWS * TK;

    static cudaStream_t s2 = nullptr;
    static cudaEvent_t e_fork = nullptr, e_join = nullptr, e_g2a = nullptr, e_ln0 = nullptr;
    if (!s2) {
        cudaStreamCreateWithFlags(&s2, cudaStreamNonBlocking);
        cudaEventCreateWithFlags(&e_fork, cudaEventDisableTiming);
        cudaEventCreateWithFlags(&e_join, cudaEventDisableTiming);
        cudaEventCreateWithFlags(&e_g2a, cudaEventDisableTiming);
        cudaEventCreateWithFlags(&e_ln0, cudaEventDisableTiming);
    }

    cudaEventRecord(e_fork, 0);
    cudaStreamWaitEvent(s2, e_fork, 0);

    // Chain A (s2): stats -> topk -> split-K selproj -> reduce
    stats_kernel<<<MKEYS / 8, 256, 0, s2>>>(mk);
    topk_part<<<dim3(16, 2), 1024, 0, s2>>>();
    topk_merge<<<2, 512, 0, s2>>>();
    selproj_part<<<dim3(16, 16, 2), 256, 0, s2>>>(mk, mv, Wk, Wv);
    selproj_reduce<<<2 * 64 * DIM / 256, 256, 0, s2>>>();
    cudaEventRecord(e_join, s2);

    // Chain B (main): q-projection GEMM (with qm partials)
    mma_gemm<<<dim3(8, 16), 256>>>(q, Wq, p_qfull, nullptr, p_qmp, 0);

    // join, then attention (full rows)
    cudaStreamWaitEvent(0, e_join, 0);
    attn_scores<<<dim3(NH, NROWS / 64), 256>>>();
    attn_ctx<<<NROWS / 16, 256>>>(out_avg, out_sel);

    // gemm2 in two m-halves on main; LN of half 0 overlaps gemm2 half 1 on s2
    mma_gemm<<<dim3(8, 8), 256>>>(p_ctx, Wo, p_qfull, bo, nullptr, 0);
    cudaEventRecord(e_g2a, 0);
    cudaStreamWaitEvent(s2, e_g2a, 0);
    ln_kernel<<<NROWS / 2, 256, 0, s2>>>(0, p_qfull, gamma, beta, out_main);
    cudaEventRecord(e_ln0, s2);

    mma_gemm<<<dim3(8, 8), 256>>>(p_ctx, Wo, p_qfull, bo, nullptr, 1024);
    ln_kernel<<<NROWS / 2, 256>>>(1024, p_qfull, gamma, beta, out_main);
    cudaStreamWaitEvent(0, e_ln0, 0);
    (void)in_sizes; (void)n_in; (void)out_size;
}

// round 16
// speedup vs baseline: 1.2300x; 1.2300x over previous
#include <cuda_runtime.h>
#include <cuda_bf16.h>
#include <math.h>
#include <stdint.h>

// Problem constants
#define NROWS 2048      // B*N
#define DIM   1024      // D
#define MKEYS 32768     // M
#define TK    32        // top-k
#define NH    16        // heads
#define HDIM  64        // head dim

// ================= scratch (device globals) =================
__device__ float g_qfull[NROWS * DIM];
__device__ float g_ctx[NROWS * DIM];
__device__ float g_c[MKEYS];
__device__ int   g_sel[2][TK];
__device__ float g_Kt[2][DIM * TK];      // projected keys, transposed [o][k]
__device__ float g_V[2][TK * DIM];       // projected values [k][o]
__device__ float g_att[NROWS * (NH * TK)];
__device__ unsigned long long g_part[2][16][TK];
__device__ float g_qmp[8 * NROWS];
__device__ float g_pp[2 * 16 * 64 * DIM];   // selproj partials [kv][ds][row64][o]

// ================= PTX helpers =================
__device__ __forceinline__ uint32_t smem_u32(const void* p) {
    uint32_t a;
    asm("{ .reg .u64 t; cvta.to.shared.u64 t, %1; cvt.u32.u64 %0, t; }" : "=r"(a) : "l"(p));
    return a;
}
__device__ __forceinline__ void ldsm4(uint32_t* r, uint32_t addr) {
    asm volatile("ldmatrix.sync.aligned.m8n8.x4.shared.b16 {%0,%1,%2,%3}, [%4];"
        : "=r"(r[0]), "=r"(r[1]), "=r"(r[2]), "=r"(r[3]) : "r"(addr));
}
__device__ __forceinline__ void mma16816(float* c, const uint32_t* a, const uint32_t* b) {
    asm volatile("mma.sync.aligned.m16n8k16.row.col.f32.bf16.bf16.f32 "
        "{%0,%1,%2,%3}, {%4,%5,%6,%7}, {%8,%9}, {%0,%1,%2,%3};"
        : "+f"(c[0]), "+f"(c[1]), "+f"(c[2]), "+f"(c[3])
        : "r"(a[0]), "r"(a[1]), "r"(a[2]), "r"(a[3]), "r"(b[0]), "r"(b[1]));
}
__device__ __forceinline__ uint32_t cvt_bf2(float lo, float hi) {
    uint32_t r;
    asm("cvt.rn.bf16x2.f32 %0, %1, %2;" : "=r"(r) : "f"(hi), "f"(lo));
    return r;
}

// ================= 1) per-memory-row stats =================
__global__ void stats_kernel(const float* __restrict__ keys) {
    int warp = (blockIdx.x * blockDim.x + threadIdx.x) >> 5;
    int lane = threadIdx.x & 31;
    if (warp >= MKEYS) return;
    const float4* p = (const float4*)(keys + (size_t)warp * DIM);
    float s = 0.f, sq = 0.f;
#pragma unroll
    for (int i = 0; i < 8; i++) {
        float4 v = p[lane + i * 32];
        s  += v.x + v.y + v.z + v.w;
        sq += v.x * v.x + v.y * v.y + v.z * v.z + v.w * v.w;
    }
#pragma unroll
    for (int o = 16; o; o >>= 1) {
        s  += __shfl_xor_sync(0xffffffffu, s, o);
        sq += __shfl_xor_sync(0xffffffffu, sq, o);
    }
    if (lane == 0) g_c[warp] = s / (32.0f * sqrtf(sq));
}

// ================= 2) top-32 =================
__device__ __forceinline__ unsigned long long tk_make_key(float f, int m) {
    unsigned b = __float_as_uint(f);
    unsigned k = (b & 0x80000000u) ? ~b : (b | 0x80000000u);
    return ((unsigned long long)k << 32) | (unsigned long long)(0xFFFFFFFFu - (unsigned)m);
}
__device__ __forceinline__ unsigned long long tk_sort_asc(unsigned long long v) {
    unsigned lane = threadIdx.x & 31;
#pragma unroll
    for (int k = 2; k <= 32; k <<= 1) {
#pragma unroll
        for (int j = k >> 1; j > 0; j >>= 1) {
            unsigned long long o = __shfl_xor_sync(0xffffffffu, v, j);
            bool up = ((lane & k) == 0), lower = ((lane & j) == 0);
            unsigned long long mn = v < o ? v : o, mx = v < o ? o : v;
            v = (up == lower) ? mn : mx;
        }
    }
    return v;
}
__device__ __forceinline__ unsigned long long tk_bmerge_asc(unsigned long long v) {
    unsigned lane = threadIdx.x & 31;
#pragma unroll
    for (int j = 16; j > 0; j >>= 1) {
        unsigned long long o = __shfl_xor_sync(0xffffffffu, v, j);
        unsigned long long mn = v < o ? v : o, mx = v < o ? o : v;
        v = ((lane & j) == 0) ? mn : mx;
    }
    return v;
}
__global__ void __launch_bounds__(1024) topk_part() {
    int set = blockIdx.y, p = blockIdx.x;
    int lane = threadIdx.x & 31, w = threadIdx.x >> 5;
    __shared__ unsigned long long sh[32][33];
    float sgn = set ? -1.f : 1.f;
    int base = p * 2048 + w * 64;
    int i0 = base + lane, i1 = base + 32 + lane;
    float f0 = sgn * g_c[i0], f1 = sgn * g_c[i1];
    unsigned long long a = tk_sort_asc(tk_make_key(f0, i0));
    unsigned long long b = tk_sort_asc(tk_make_key(f1, i1));
    unsigned long long o = __shfl_sync(0xffffffffu, b, 31 - lane);
    unsigned long long v = a > o ? a : o;
    a = tk_bmerge_asc(v);
    sh[w][lane] = a;
    __syncthreads();
#pragma unroll
    for (int st = 1; st < 32; st <<= 1) {
        if (w < 16 / st) {
            unsigned long long A = sh[2 * w * st][lane];
            unsigned long long B = sh[(2 * w + 1) * st][31 - lane];
            unsigned long long m = A > B ? A : B;
            m = tk_bmerge_asc(m);
            sh[2 * w * st][lane] = m;
        }
        __syncthreads();
    }
    if (w == 0) g_part[set][p][lane] = sh[0][lane];
}
__global__ void __launch_bounds__(512) topk_merge() {
    int set = blockIdx.x;
    int lane = threadIdx.x & 31, w = threadIdx.x >> 5;
    __shared__ unsigned long long sh[16][33];
    sh[w][lane] = g_part[set][w][lane];
    __syncthreads();
#pragma unroll
    for (int st = 1; st < 16; st <<= 1) {
        if (w < 8 / st) {
            unsigned long long A = sh[2 * w * st][lane];
            unsigned long long B = sh[(2 * w + 1) * st][31 - lane];
            unsigned long long m = A > B ? A : B;
            m = tk_bmerge_asc(m);
            sh[2 * w * st][lane] = m;
        }
        __syncthreads();
    }
    if (w == 0) {
        unsigned long long v = sh[0][lane];
        int m = (int)(0xFFFFFFFFu - (unsigned)(v & 0xFFFFFFFFull));
        g_sel[set][31 - lane] = m;
    }
}

// ================= 3) HMMA bf16x3 GEMM with fused fp32->hi/lo split =================
// round-13 proven structure: single buffer, static smem, 2 syncs/iter, grid dim3(8,16)
#define BK 32
#define NK (DIM / BK)
#define SSTRIDE 40

__global__ void __launch_bounds__(256) mma_gemm(
    const float* __restrict__ A, const float* __restrict__ B,
    float* __restrict__ C, const float* __restrict__ bias,
    float* __restrict__ qmp) {
    __shared__ __align__(16) __nv_bfloat16 sm[4][128 * SSTRIDE];
    __shared__ float sq[4][128];
    int tid = threadIdx.x, lane = tid & 31, wid = tid >> 5;
    int bm = blockIdx.y * 128, bn = blockIdx.x * 128;
    int wm = wid >> 2, wn = wid & 3;
    int m0 = wm * 64, n0 = wn * 32;

    const float* srcs[2] = { A + (size_t)bm * DIM, B + (size_t)bn * DIM };

    uint32_t sbase[4];
#pragma unroll
    for (int t = 0; t < 4; t++) sbase[t] = smem_u32(sm[t]);

    int a_ro = (m0 + (lane & 15)) * SSTRIDE + ((lane & 16) ? 8 : 0);
    int b_ro = (n0 + (lane & 7) + ((lane & 16) ? 8 : 0)) * SSTRIDE + ((lane & 8) ? 8 : 0);

    float acc[4][4][4];
#pragma unroll
    for (int i = 0; i < 4; i++)
#pragma unroll
        for (int j = 0; j < 4; j++)
#pragma unroll
            for (int r = 0; r < 4; r++) acc[i][j][r] = 0.f;

    float4 pf[8];
#pragma unroll
    for (int t = 0; t < 2; t++)
#pragma unroll
        for (int u = 0; u < 4; u++) {
            int c = tid + u * 256, row = c >> 3, fc = c & 7;
            pf[t * 4 + u] = *(const float4*)(srcs[t] + (size_t)row * DIM + fc * 4);
        }

#pragma unroll 1
    for (int kt = 0; kt < NK; kt++) {
#pragma unroll
        for (int t = 0; t < 2; t++)
#pragma unroll
            for (int u = 0; u < 4; u++) {
                int c = tid + u * 256, row = c >> 3, fc = c & 7;
                float4 v = pf[t * 4 + u];
                uint32_t h01 = cvt_bf2(v.x, v.y), h23 = cvt_bf2(v.z, v.w);
                float l0 = v.x - __uint_as_float(h01 << 16);
                float l1 = v.y - __uint_as_float(h01 & 0xFFFF0000u);
                float l2 = v.z - __uint_as_float(h23 << 16);
                float l3 = v.w - __uint_as_float(h23 & 0xFFFF0000u);
                uint32_t l01 = cvt_bf2(l0, l1), l23 = cvt_bf2(l2, l3);
                *(uint2*)(&sm[t * 2][row * SSTRIDE + fc * 4]) = make_uint2(h01, h23);
                *(uint2*)(&sm[t * 2 + 1][row * SSTRIDE + fc * 4]) = make_uint2(l01, l23);
            }
        __syncthreads();
        if (kt + 1 < NK) {
#pragma unroll
            for (int t = 0; t < 2; t++)
#pragma unroll
                for (int u = 0; u < 4; u++) {
                    int c = tid + u * 256, row = c >> 3, fc = c & 7;
                    pf[t * 4 + u] = *(const float4*)(srcs[t] + (size_t)row * DIM + (kt + 1) * BK + fc * 4);
                }
        }
#pragma unroll
        for (int ks = 0; ks < 2; ks++) {
            uint32_t ah[4][4], al[4][4];
#pragma unroll
            for (int mt = 0; mt < 4; mt++) {
                uint32_t off = 2u * (uint32_t)(a_ro + mt * 16 * SSTRIDE + ks * 16);
                ldsm4(ah[mt], sbase[0] + off);
                ldsm4(al[mt], sbase[1] + off);
            }
            uint32_t bh[4][2], bl[4][2];
#pragma unroll
            for (int pr = 0; pr < 2; pr++) {
                uint32_t off = 2u * (uint32_t)(b_ro + pr * 16 * SSTRIDE + ks * 16);
                uint32_t r[4];
                ldsm4(r, sbase[2] + off);
                bh[pr * 2][0] = r[0]; bh[pr * 2][1] = r[1];
                bh[pr * 2 + 1][0] = r[2]; bh[pr * 2 + 1][1] = r[3];
                ldsm4(r, sbase[3] + off);
                bl[pr * 2][0] = r[0]; bl[pr * 2][1] = r[1];
                bl[pr * 2 + 1][0] = r[2]; bl[pr * 2 + 1][1] = r[3];
            }
#pragma unroll
            for (int mt = 0; mt < 4; mt++)
#pragma unroll
                for (int nt = 0; nt < 4; nt++) {
                    mma16816(acc[mt][nt], ah[mt], bh[nt]);
                    mma16816(acc[mt][nt], ah[mt], bl[nt]);
                    mma16816(acc[mt][nt], al[mt], bh[nt]);
                }
        }
        __syncthreads();
    }

    int gid = lane >> 2, tig = lane & 3;
#pragma unroll
    for (int mt = 0; mt < 4; mt++)
#pragma unroll
        for (int nt = 0; nt < 4; nt++) {
            int row = bm + m0 + mt * 16 + gid;
            int col = bn + n0 + nt * 8 + tig * 2;
            float b0 = 0.f, b1 = 0.f;
            if (bias) { b0 = bias[col]; b1 = bias[col + 1]; }
            float2 v0 = make_float2(acc[mt][nt][0] + b0, acc[mt][nt][1] + b1);
            float2 v1 = make_float2(acc[mt][nt][2] + b0, acc[mt][nt][3] + b1);
            *(float2*)(C + (size_t)row * DIM + col) = v0;
            *(float2*)(C + (size_t)(row + 8) * DIM + col) = v1;
        }

    if (qmp) {
#pragma unroll
        for (int mt = 0; mt < 4; mt++) {
            float p0 = 0.f, p1 = 0.f;
#pragma unroll
            for (int nt = 0; nt < 4; nt++) {
                p0 += acc[mt][nt][0] + acc[mt][nt][1];
                p1 += acc[mt][nt][2] + acc[mt][nt][3];
            }
            p0 += __shfl_xor_sync(0xffffffffu, p0, 1);
            p0 += __shfl_xor_sync(0xffffffffu, p0, 2);
            p1 += __shfl_xor_sync(0xffffffffu, p1, 1);
            p1 += __shfl_xor_sync(0xffffffffu, p1, 2);
            if (tig == 0) {
                sq[wn][m0 + mt * 16 + gid] = p0;
                sq[wn][m0 + mt * 16 + gid + 8] = p1;
            }
        }
        __syncthreads();
        if (tid < 128) {
            float s = sq[0][tid] + sq[1][tid] + sq[2][tid] + sq[3][tid];
            qmp[(size_t)blockIdx.x * NROWS + bm + tid] = s;
        }
    }
}

// ================= 4) selproj split-K + reduce =================
__global__ void __launch_bounds__(256) selproj_part(const float* __restrict__ keys,
                                                    const float* __restrict__ vals,
                                                    const float* __restrict__ Wk,
                                                    const float* __restrict__ Wv) {
    int o0 = blockIdx.x * 64, ds = blockIdx.y, kv = blockIdx.z;
    int d0 = ds * 64;
    const float* S = kv ? vals : keys;
    const float* W = kv ? Wv : Wk;
    __shared__ float Ss[64][68];
    __shared__ float Wt[64][65];
    __shared__ int sel[64];
    int tid = threadIdx.x;
    if (tid < 64) sel[tid] = g_sel[tid >> 5][tid & 31];
    __syncthreads();
#pragma unroll
    for (int u = 0; u < 4; u++) {
        int c = tid + u * 256;
        int r = c >> 4, c4 = c & 15;
        float4 v = *(const float4*)(S + (size_t)sel[r] * DIM + d0 + c4 * 4);
        *(float4*)(&Ss[r][c4 * 4]) = v;
    }
#pragma unroll
    for (int u = 0; u < 4; u++) {
        int c = tid + u * 256;
        int orow = c >> 4, c4 = c & 15;
        float4 v = *(const float4*)(W + (size_t)(o0 + orow) * DIM + d0 + c4 * 4);
        Wt[c4 * 4 + 0][orow] = v.x;
        Wt[c4 * 4 + 1][orow] = v.y;
        Wt[c4 * 4 + 2][orow] = v.z;
        Wt[c4 * 4 + 3][orow] = v.w;
    }
    __syncthreads();

    int ol = tid & 63, rbase = (tid >> 6) * 16;
    float acc[16];
#pragma unroll
    for (int i = 0; i < 16; i++) acc[i] = 0.f;
#pragma unroll 1
    for (int d = 0; d < 64; d += 4) {
        float w0 = Wt[d][ol], w1 = Wt[d + 1][ol], w2 = Wt[d + 2][ol], w3 = Wt[d + 3][ol];
#pragma unroll
        for (int r = 0; r < 16; r++) {
            float4 s = *(const float4*)(&Ss[rbase + r][d]);
            acc[r] += s.x * w0 + s.y * w1 + s.z * w2 + s.w * w3;
        }
    }
    float* dst = g_pp + ((size_t)(kv * 16 + ds) * 64) * DIM;
#pragma unroll
    for (int r = 0; r < 16; r++)
        dst[(size_t)(rbase + r) * DIM + o0 + ol] = acc[r];
}

__global__ void __launch_bounds__(256) selproj_reduce() {
    int idx = blockIdx.x * 256 + threadIdx.x;
    int kv = idx >> 16;
    int rem = idx & 65535;
    int r = rem >> 10, o = rem & 1023;
    const float* src = g_pp + (size_t)(kv * 16) * 64 * DIM + (size_t)r * DIM + o;
    float s = 0.f;
#pragma unroll
    for (int ds = 0; ds < 16; ds++) s += src[(size_t)ds * 64 * DIM];
    int set = r >> 5, k = r & 31;
    if (kv == 0) g_Kt[set][(size_t)o * TK + k] = s;
    else         g_V[set][(size_t)k * DIM + o] = s;
}

// ================= 5a) attention scores + softmax (qm folded) =================
__global__ void __launch_bounds__(256) attn_scores() {
    int h = blockIdx.x;
    int r0 = blockIdx.y * 64;
    __shared__ float qs[64][65];
    __shared__ float Ks[2][64][33];
    __shared__ int sets[64];
    int tid = threadIdx.x;
#pragma unroll
    for (int u = 0; u < 4; u++) {
        int c = tid + u * 256;
        int r = c >> 4, q4 = c & 15;
        float4 v = *(const float4*)(g_qfull + (size_t)(r0 + r) * DIM + h * HDIM + q4 * 4);
        qs[r][q4 * 4 + 0] = v.x; qs[r][q4 * 4 + 1] = v.y; qs[r][q4 * 4 + 2] = v.z; qs[r][q4 * 4 + 3] = v.w;
    }
#pragma unroll
    for (int u = 0; u < 4; u++) {
        int c = tid + u * 256;
        int s = c >> 9, rem = c & 511, j = rem >> 3, k4 = rem & 7;
        float4 v = *(const float4*)(&g_Kt[s][(size_t)(h * HDIM + j) * TK + k4 * 4]);
        Ks[s][j][k4 * 4 + 0] = v.x; Ks[s][j][k4 * 4 + 1] = v.y; Ks[s][j][k4 * 4 + 2] = v.z; Ks[s][j][k4 * 4 + 3] = v.w;
    }
    if (tid < 64) {
        float ss = 0.f;
#pragma unroll
        for (int j = 0; j < 8; j++) ss += g_qmp[(size_t)j * NROWS + r0 + tid];
        sets[tid] = (ss >= 0.f) ? 0 : 1;
    }
    __syncthreads();
    int r = tid >> 2, kg = tid & 3;
    int s = sets[r];
    float sc[8];
#pragma unroll
    for (int kk = 0; kk < 8; kk++) sc[kk] = 0.f;
#pragma unroll
    for (int j = 0; j < 64; j++) {
        float qv = qs[r][j];
#pragma unroll
        for (int kk = 0; kk < 8; kk++) sc[kk] += qv * Ks[s][j][kg * 8 + kk];
    }
    float mx = -INFINITY;
#pragma unroll
    for (int kk = 0; kk < 8; kk++) { sc[kk] *= 0.125f; mx = fmaxf(mx, sc[kk]); }
#pragma unroll
    for (int o = 1; o <= 2; o <<= 1) mx = fmaxf(mx, __shfl_xor_sync(0xffffffffu, mx, o));
    float e[8]; float sum = 0.f;
#pragma unroll
    for (int kk = 0; kk < 8; kk++) { e[kk] = expf(sc[kk] - mx); sum += e[kk]; }
#pragma unroll
    for (int o = 1; o <= 2; o <<= 1) sum += __shfl_xor_sync(0xffffffffu, sum, o);
    float inv = 1.f / sum;
    float* dst = &g_att[(size_t)(r0 + r) * (NH * TK) + h * TK + kg * 8];
    *(float4*)(dst)     = make_float4(e[0] * inv, e[1] * inv, e[2] * inv, e[3] * inv);
    *(float4*)(dst + 4) = make_float4(e[4] * inv, e[5] * inv, e[6] * inv, e[7] * inv);
}

// ================= 5b) context + avg_attn + sel_idx (qm folded) =================
__global__ void __launch_bounds__(256) attn_ctx(float* __restrict__ out_avg,
                                                float* __restrict__ out_sel) {
    int r0 = blockIdx.x * 16;
    __shared__ float att[16][NH * 33];
    __shared__ int sets[16];
    int tid = threadIdx.x;
    if (tid < 16) {
        float ss = 0.f;
#pragma unroll
        for (int j = 0; j < 8; j++) ss += g_qmp[(size_t)j * NROWS + r0 + tid];
        sets[tid] = (ss >= 0.f) ? 0 : 1;
    }
#pragma unroll
    for (int u = 0; u < 8; u++) {
        int c = tid + u * 256;
        int r = c >> 7, rem = c & 127;
        float4 v = *(const float4*)(&g_att[(size_t)(r0 + r) * (NH * TK) + rem * 4]);
        int hh = (rem * 4) >> 5, k = (rem * 4) & 31;
        float* d = &att[r][hh * 33 + k];
        d[0] = v.x; d[1] = v.y; d[2] = v.z; d[3] = v.w;
    }
    __syncthreads();
#pragma unroll
    for (int u = 0; u < 2; u++) {
        int c = tid + u * 256;
        int r = c >> 5, k = c & 31;
        float sm = 0.f;
#pragma unroll
        for (int hh = 0; hh < NH; hh++) sm += att[r][hh * 33 + k];
        out_avg[(size_t)(r0 + r) * TK + k] = sm * (1.f / NH);
        out_sel[(size_t)(r0 + r) * TK + k] = (float)g_sel[sets[r]][k];
    }
#pragma unroll 1
    for (int c = 0; c < 4; c++) {
        int o = c * 256 + tid;
        int h = o >> 6;
        float vv0[32], vv1[32];
#pragma unroll
        for (int k = 0; k < 32; k++) {
            vv0[k] = g_V[0][(size_t)k * DIM + o];
            vv1[k] = g_V[1][(size_t)k * DIM + o];
        }
#pragma unroll 1
        for (int r = 0; r < 16; r++) {
            const float* a = &att[r][h * 33];
            float sum = 0.f;
            if (sets[r]) {
#pragma unroll
                for (int k = 0; k < 32; k++) sum += a[k] * vv1[k];
            } else {
#pragma unroll
                for (int k = 0; k < 32; k++) sum += a[k] * vv0[k];
            }
            g_ctx[(size_t)(r0 + r) * DIM + o] = sum;
        }
    }
}

// ================= 6) LayerNorm =================
__global__ void __launch_bounds__(256) ln_kernel(const float* __restrict__ X,
                                                 const float* __restrict__ gamma,
                                                 const float* __restrict__ beta,
                                                 float* __restrict__ out) {
    int row = blockIdx.x;
    __shared__ float red[256];
    int t = threadIdx.x;
    const float* p = X + (size_t)row * DIM;
    float4 v = ((const float4*)p)[t];
    float s = v.x + v.y + v.z + v.w;
    red[t] = s; __syncthreads();
    for (int off = 128; off; off >>= 1) { if (t < off) red[t] += red[t + off]; __syncthreads(); }
    float mu = red[0] * (1.f / DIM);
    __syncthreads();
    float d0 = v.x - mu, d1 = v.y - mu, d2 = v.z - mu, d3 = v.w - mu;
    red[t] = d0 * d0 + d1 * d1 + d2 * d2 + d3 * d3;
    __syncthreads();
    for (int off = 128; off; off >>= 1) { if (t < off) red[t] += red[t + off]; __syncthreads(); }
    float inv = rsqrtf(red[0] * (1.f / DIM) + 1e-5f);
    float4 g = ((const float4*)gamma)[t];
    float4 b = ((const float4*)beta)[t];
    float4 o;
    o.x = d0 * inv * g.x + b.x;
    o.y = d1 * inv * g.y + b.y;
    o.z = d2 * inv * g.z + b.z;
    o.w = d3 * inv * g.w + b.w;
    ((float4*)(out + (size_t)row * DIM))[t] = o;
}

// ================= launch =================
extern "C" void kernel_launch(void* const* d_in, const int* in_sizes, int n_in,
                              void* d_out, int out_size) {
    const float* q    = (const float*)d_in[0];
    const float* mk   = (const float*)d_in[1];
    const float* mv   = (const float*)d_in[2];
    const float* Wq   = (const float*)d_in[3];
    const float* Wk   = (const float*)d_in[4];
    const float* Wv   = (const float*)d_in[5];
    const float* Wo   = (const float*)d_in[6];
    const float* bo   = (const float*)d_in[7];
    const float* gamma = (const float*)d_in[8];
    const float* beta  = (const float*)d_in[9];
    float* out = (float*)d_out;

    float *p_qfull, *p_ctx, *p_qmp;
    cudaGetSymbolAddress((void**)&p_qfull, g_qfull);
    cudaGetSymbolAddress((void**)&p_ctx, g_ctx);
    cudaGetSymbolAddress((void**)&p_qmp, g_qmp);

    float* out_main = out;
    float* out_avg  = out + (size_t)NROWS * DIM;
    float* out_sel  = out + (size_t)NROWS * DIM + (size_t)NROWS * TK;

    static cudaStream_t s2 = nullptr;
    static cudaEvent_t e_fork = nullptr, e_join = nullptr;
    if (!s2) {
        cudaStreamCreateWithFlags(&s2, cudaStreamNonBlocking);
        cudaEventCreateWithFlags(&e_fork, cudaEventDisableTiming);
        cudaEventCreateWithFlags(&e_join, cudaEventDisableTiming);
    }

    dim3 gq(DIM / 128, NROWS / 128);

    cudaEventRecord(e_fork, 0);
    cudaStreamWaitEvent(s2, e_fork, 0);

    // Chain A (s2): stats -> topk -> split-K selproj -> reduce
    stats_kernel<<<MKEYS / 8, 256, 0, s2>>>(mk);
    topk_part<<<dim3(16, 2), 1024, 0, s2>>>();
    topk_merge<<<2, 512, 0, s2>>>();
    selproj_part<<<dim3(16, 16, 2), 256, 0, s2>>>(mk, mv, Wk, Wv);
    selproj_reduce<<<2 * 64 * DIM / 256, 256, 0, s2>>>();
    cudaEventRecord(e_join, s2);

    // Chain B (main): q-projection GEMM (with qm partials)
    mma_gemm<<<gq, 256>>>(q, Wq, p_qfull, nullptr, p_qmp);

    // join, then attention + gemm2 + LN (full-grid launches, no splits)
    cudaStreamWaitEvent(0, e_join, 0);
    attn_scores<<<dim3(NH, NROWS / 64), 256>>>();
    attn_ctx<<<NROWS / 16, 256>>>(out_avg, out_sel);
    mma_gemm<<<gq, 256>>>(p_ctx, Wo, p_qfull, bo, nullptr);
    ln_kernel<<<NROWS, 256>>>(p_qfull, gamma, beta, out_main);
    (void)in_sizes; (void)n_in; (void)out_size;
}